// round 8
// baseline (speedup 1.0000x reference)
#include <cuda_runtime.h>
#include <math.h>
#include <stdint.h>

// Problem constants
static constexpr int D    = 768;
static constexpr int H    = 12;
static constexpr int HD   = 64;
static constexpr int DFF  = 3072;
static constexpr int B    = 2;
static constexpr int S    = 4096;
static constexpr int NTOK = B * S;   // 8192
static constexpr int QKVW = 3 * D;   // 2304

// ---------------- scratch (static device globals; no allocation) ------------
__device__ float g_h   [NTOK * D];
__device__ float g_qkv [NTOK * QKVW];
__device__ float g_ctx [NTOK * D];
__device__ float g_x1  [NTOK * D];
__device__ float g_h2  [NTOK * D];
__device__ float g_ff  [NTOK * DFF];
__device__ float g_wqkv[D * QKVW];
__device__ float g_bqkv[QKVW];

// ---------------- cp.async helpers ------------------------------------------
#define CP16(dst_u32, src_ptr)                                                 \
    asm volatile("cp.async.cg.shared.global [%0], [%1], 16;"                   \
                 :: "r"(dst_u32), "l"(src_ptr))
#define CP_COMMIT() asm volatile("cp.async.commit_group;")
#define CP_WAIT(N)  asm volatile("cp.async.wait_group %0;" :: "n"(N))

// ---------------- tf32 helpers ----------------------------------------------
__device__ __forceinline__ uint32_t tf32u(float x) {
    asm("cvt.rna.tf32.f32 %0, %0;" : "+f"(x));
    return __float_as_uint(x);
}

#define MMA_TF32(Cr, Ar, B0, B1)                                               \
    asm volatile(                                                              \
        "mma.sync.aligned.m16n8k8.row.col.f32.tf32.tf32.f32 "                  \
        "{%0,%1,%2,%3}, {%4,%5,%6,%7}, {%8,%9}, {%0,%1,%2,%3};"                \
        : "+f"(Cr[0]), "+f"(Cr[1]), "+f"(Cr[2]), "+f"(Cr[3])                   \
        : "r"(Ar[0]), "r"(Ar[1]), "r"(Ar[2]), "r"(Ar[3]),                      \
          "r"(B0), "r"(B1))

// ---------------- weight packing for fused QKV -------------------------------
__global__ __launch_bounds__(256) void pack_qkv_w(
    const float* __restrict__ Wq, const float* __restrict__ Wk,
    const float* __restrict__ Wv, float* __restrict__ Wp)
{
    int idx = blockIdx.x * 256 + threadIdx.x;   // over D*D
    if (idx >= D * D) return;
    int row = idx / D, col = idx % D;
    float* o = Wp + (size_t)row * QKVW + col;
    o[0]       = Wq[idx];
    o[D]       = Wk[idx];
    o[2 * D]   = Wv[idx];
}
__global__ __launch_bounds__(256) void pack_qkv_b(
    const float* __restrict__ bq, const float* __restrict__ bk,
    const float* __restrict__ bv, float* __restrict__ bp)
{
    int i = blockIdx.x * 256 + threadIdx.x;
    if (i < D) { bp[i] = bq[i]; bp[i + D] = bk[i]; bp[i + 2 * D] = bv[i]; }
}

// ---------------- LayerNorm: one block per row, 256 threads -----------------
__global__ __launch_bounds__(256) void ln_kernel(
    const float* __restrict__ x,
    const float* __restrict__ gamma,
    const float* __restrict__ beta,
    float* __restrict__ out)
{
    int row = blockIdx.x;
    int tid = threadIdx.x;
    const float* xr = x + (size_t)row * D;

    float v0 = xr[tid];
    float v1 = xr[tid + 256];
    float v2 = xr[tid + 512];
    float s  = v0 + v1 + v2;
    float ss = v0*v0 + v1*v1 + v2*v2;

    #pragma unroll
    for (int off = 16; off; off >>= 1) {
        s  += __shfl_down_sync(0xffffffffu, s,  off);
        ss += __shfl_down_sync(0xffffffffu, ss, off);
    }

    __shared__ float rs[8], rss[8];
    __shared__ float mu_s, rstd_s;
    if ((tid & 31) == 0) { rs[tid >> 5] = s; rss[tid >> 5] = ss; }
    __syncthreads();
    if (tid == 0) {
        float S_ = 0.f, SS_ = 0.f;
        #pragma unroll
        for (int w = 0; w < 8; w++) { S_ += rs[w]; SS_ += rss[w]; }
        float mu  = S_ * (1.0f / (float)D);
        float var = SS_ * (1.0f / (float)D) - mu * mu;
        mu_s   = mu;
        rstd_s = rsqrtf(var + 1e-5f);
    }
    __syncthreads();
    float mu = mu_s, r = rstd_s;

    float* orow = out + (size_t)row * D;
    orow[tid]       = (v0 - mu) * r * gamma[tid]       + beta[tid];
    orow[tid + 256] = (v1 - mu) * r * gamma[tid + 256] + beta[tid + 256];
    orow[tid + 512] = (v2 - mu) * r * gamma[tid + 512] + beta[tid + 512];
}

// ---------------- tf32 MMA GEMM, cp.async 4-stage, 1 sync/iter --------------
// 128x128 tile, BK=16, 8 warps (2x4), warp tile 64x32.
// EPI: 0 = bias, 1 = bias+relu, 2 = bias+residual, 3 = bias+tf32-round
static constexpr int GA_STR = 20;
static constexpr int GB_STR = 136;
static constexpr int GA_SZ  = 128 * GA_STR;            // 2560 floats
static constexpr int GB_SZ  = 16 * GB_STR;             // 2176 floats
static constexpr int G_STG  = GA_SZ + GB_SZ;           // 4736 floats/stage
static constexpr int G_NSTG = 4;
static constexpr int GEMM_SMEM = G_NSTG * G_STG * 4;   // 75776 bytes

template <int EPI>
__global__ __launch_bounds__(256, 2) void mma_gemm(
    int M, int N, int K,
    const float* __restrict__ A,
    const float* __restrict__ Bw,
    const float* __restrict__ bias,
    const float* __restrict__ res,
    float* __restrict__ C)
{
    extern __shared__ float sm[];

    int tid  = threadIdx.x;
    int lane = tid & 31;
    int warp = tid >> 5;
    int wm   = warp >> 2;
    int wn   = warp & 3;
    int gid  = lane >> 2;
    int tig  = lane & 3;

    int bx = blockIdx.x, by = blockIdx.y;
    const float* Ab = A  + (size_t)(by * 128) * K;
    const float* Bb = Bw + bx * 128;

    int arow = tid >> 2;            // 0..63 (+64)
    int acol = (tid & 3) * 4;
    int brow = tid >> 4;            // 0..15
    int bcol = (tid & 15) * 4;      // 0..60 (+64)

    const float* ag0 = Ab + (size_t)arow * K + acol;
    const float* ag1 = Ab + (size_t)(arow + 64) * K + acol;
    const float* bg0 = Bb + (size_t)brow * N + bcol;

    uint32_t smb = (uint32_t)__cvta_generic_to_shared(sm);
    uint32_t aoff0 = (arow * GA_STR + acol) * 4;
    uint32_t aoff1 = ((arow + 64) * GA_STR + acol) * 4;
    uint32_t boff0 = (GA_SZ + brow * GB_STR + bcol) * 4;
    uint32_t boff1 = boff0 + 64 * 4;

    auto issue = [&](int t) {
        uint32_t s = smb + (uint32_t)((t & 3) * G_STG * 4);
        CP16(s + aoff0, ag0 + t * 16);
        CP16(s + aoff1, ag1 + t * 16);
        const float* bp = bg0 + (size_t)t * 16 * N;
        CP16(s + boff0, bp);
        CP16(s + boff1, bp + 64);
        CP_COMMIT();
    };

    float acc[4][4][4];
    #pragma unroll
    for (int i = 0; i < 4; i++)
        #pragma unroll
        for (int j = 0; j < 4; j++)
            #pragma unroll
            for (int r = 0; r < 4; r++) acc[i][j][r] = 0.f;

    int ntiles = K >> 4;   // >= 48 always here
    issue(0);
    issue(1);
    issue(2);

    for (int t = 0; t < ntiles; t++) {
        CP_WAIT(2);
        __syncthreads();
        // one commit per iteration keeps wait_group(2) semantics exact
        if (t + 3 < ntiles) issue(t + 3); else CP_COMMIT();

        const float* As = sm + (t & 3) * G_STG;
        const float* Bs = As + GA_SZ;

        #pragma unroll
        for (int ks = 0; ks < 2; ks++) {
            int k0 = ks * 8;
            uint32_t af[4][4];
            uint32_t bf[4][2];
            #pragma unroll
            for (int ma = 0; ma < 4; ma++) {
                int r = wm * 64 + ma * 16 + gid;
                af[ma][0] = tf32u(As[r * GA_STR + k0 + tig]);
                af[ma][1] = tf32u(As[(r + 8) * GA_STR + k0 + tig]);
                af[ma][2] = tf32u(As[r * GA_STR + k0 + tig + 4]);
                af[ma][3] = tf32u(As[(r + 8) * GA_STR + k0 + tig + 4]);
            }
            #pragma unroll
            for (int na = 0; na < 4; na++) {
                int c = wn * 32 + na * 8 + gid;
                bf[na][0] = tf32u(Bs[(k0 + tig) * GB_STR + c]);
                bf[na][1] = tf32u(Bs[(k0 + tig + 4) * GB_STR + c]);
            }
            #pragma unroll
            for (int ma = 0; ma < 4; ma++)
                #pragma unroll
                for (int na = 0; na < 4; na++)
                    MMA_TF32(acc[ma][na], af[ma], bf[na][0], bf[na][1]);
        }
        // no trailing sync: with 4 stages, issue(t+3) at iter t writes buffer
        // (t-1)%4 whose readers all passed the sync at the top of this iter.
    }

    #pragma unroll
    for (int ma = 0; ma < 4; ma++) {
        #pragma unroll
        for (int na = 0; na < 4; na++) {
            int row = by * 128 + wm * 64 + ma * 16 + gid;
            int col = bx * 128 + wn * 32 + na * 8 + 2 * tig;
            float b0v = bias[col], b1v = bias[col + 1];
            float v0 = acc[ma][na][0] + b0v;
            float v1 = acc[ma][na][1] + b1v;
            float v2 = acc[ma][na][2] + b0v;
            float v3 = acc[ma][na][3] + b1v;
            if (EPI == 1) {
                v0 = fmaxf(v0, 0.f); v1 = fmaxf(v1, 0.f);
                v2 = fmaxf(v2, 0.f); v3 = fmaxf(v3, 0.f);
            }
            if (EPI == 2) {
                const float* r0 = res + (size_t)row * N + col;
                const float* r1 = res + (size_t)(row + 8) * N + col;
                v0 += r0[0]; v1 += r0[1];
                v2 += r1[0]; v3 += r1[1];
            }
            if (EPI == 3) {
                v0 = __uint_as_float(tf32u(v0));
                v1 = __uint_as_float(tf32u(v1));
                v2 = __uint_as_float(tf32u(v2));
                v3 = __uint_as_float(tf32u(v3));
            }
            *(float2*)(C + (size_t)row * N + col)       = make_float2(v0, v1);
            *(float2*)(C + (size_t)(row + 8) * N + col) = make_float2(v2, v3);
        }
    }
}

// ---------------- Flash attention, tf32 MMA + cp.async double buffer --------
// grid = (S/128, H, B), block = 256 (8 warps), 16 query rows per warp.
// Reads fused QKV buffer (row stride 2304, q|k|v at +0|+768|+1536), values
// already tf32-rounded by the QKV GEMM epilogue -> mma truncation is lossless.
static constexpr int F_STR  = 68;
static constexpr int F_TSZ  = 64 * F_STR;
static constexpr int F_STG  = 2 * F_TSZ;
static constexpr int FLASH_SMEM = 2 * F_STG * 4;

__global__ __launch_bounds__(256, 1) void flash_mma(
    const float* __restrict__ QKV,
    const int*   __restrict__ am,
    float* __restrict__ O)
{
    extern __shared__ float sm[];
    __shared__ float addm[2][64];

    const unsigned FULL = 0xffffffffu;
    int qb = blockIdx.x, h = blockIdx.y, b = blockIdx.z;
    int tid  = threadIdx.x;
    int lane = tid & 31;
    int warp = tid >> 5;
    int gid  = lane >> 2;
    int tig  = lane & 3;

    int row0 = qb * 128 + warp * 16;
    int r1 = row0 + gid;
    int r2 = r1 + 8;
    int wrow_max = row0 + 15;

    const float scale = 0.125f;

    // cooperative KV load mapping
    int lr = tid >> 2;
    int lc = (tid & 3) * 16;
    uint32_t smb = (uint32_t)__cvta_generic_to_shared(sm);
    uint32_t koff = (lr * F_STR + lc) * 4;
    uint32_t voff = (F_TSZ + lr * F_STR + lc) * 4;
    const float* kg = QKV + ((size_t)b * S + lr) * QKVW + D     + h * HD + lc;
    const float* vg = QKV + ((size_t)b * S + lr) * QKVW + 2 * D + h * HD + lc;

    auto issueKV = [&](int t) {
        uint32_t s = smb + (uint32_t)((t & 1) * F_STG * 4);
        const float* kp = kg + (size_t)t * 64 * QKVW;
        const float* vp = vg + (size_t)t * 64 * QKVW;
        #pragma unroll
        for (int i = 0; i < 16; i += 4) {
            CP16(s + koff + i * 4, kp + i);
            CP16(s + voff + i * 4, vp + i);
        }
        CP_COMMIT();
    };

    // Q fragments, pre-scaled tf32
    uint32_t qa[8][4];
    {
        const float* q1 = QKV + ((size_t)b * S + r1) * QKVW + h * HD;
        const float* q2 = QKV + ((size_t)b * S + r2) * QKVW + h * HD;
        #pragma unroll
        for (int ka = 0; ka < 8; ka++) {
            qa[ka][0] = tf32u(q1[ka * 8 + tig]     * scale);
            qa[ka][1] = tf32u(q2[ka * 8 + tig]     * scale);
            qa[ka][2] = tf32u(q1[ka * 8 + tig + 4] * scale);
            qa[ka][3] = tf32u(q2[ka * 8 + tig + 4] * scale);
        }
    }

    float m1 = -1e30f, m2 = -1e30f, l1 = 0.f, l2 = 0.f;
    float oacc[8][4];
    #pragma unroll
    for (int i = 0; i < 8; i++)
        #pragma unroll
        for (int j = 0; j < 4; j++) oacc[i][j] = 0.f;

    int ntiles = qb * 2 + 2;
    issueKV(0);
    if (tid < 64)
        addm[0][tid] = (am[(size_t)b * S + tid] != 0) ? 0.f : -1e30f;

    for (int kv = 0; kv < ntiles; kv++) {
        CP_WAIT(0);
        __syncthreads();
        if (kv + 1 < ntiles) {
            issueKV(kv + 1);
            if (tid < 64)
                addm[(kv + 1) & 1][tid] =
                    (am[(size_t)b * S + (kv + 1) * 64 + tid] != 0) ? 0.f : -1e30f;
        }

        if (kv * 64 <= wrow_max) {
            const float* Ks = sm + (kv & 1) * F_STG;
            const float* Vs = Ks + F_TSZ;
            const float* amr = addm[kv & 1];

            // ---- S = Q @ K^T ----
            float sc[8][4];
            #pragma unroll
            for (int na = 0; na < 8; na++)
                #pragma unroll
                for (int j = 0; j < 4; j++) sc[na][j] = 0.f;

            #pragma unroll
            for (int ka = 0; ka < 8; ka++) {
                #pragma unroll
                for (int na = 0; na < 8; na++) {
                    uint32_t b0 = __float_as_uint(Ks[(na * 8 + gid) * F_STR + ka * 8 + tig]);
                    uint32_t b1 = __float_as_uint(Ks[(na * 8 + gid) * F_STR + ka * 8 + tig + 4]);
                    MMA_TF32(sc[na], qa[ka], b0, b1);
                }
            }

            // ---- mask + row max ----
            float mt1 = -1e30f, mt2 = -1e30f;
            #pragma unroll
            for (int na = 0; na < 8; na++) {
                int key0 = kv * 64 + na * 8 + 2 * tig;
                float a0 = amr[na * 8 + 2 * tig];
                float a1 = amr[na * 8 + 2 * tig + 1];
                sc[na][0] = (key0     <= r1) ? sc[na][0] + a0 : -1e30f;
                sc[na][1] = (key0 + 1 <= r1) ? sc[na][1] + a1 : -1e30f;
                sc[na][2] = (key0     <= r2) ? sc[na][2] + a0 : -1e30f;
                sc[na][3] = (key0 + 1 <= r2) ? sc[na][3] + a1 : -1e30f;
                mt1 = fmaxf(mt1, fmaxf(sc[na][0], sc[na][1]));
                mt2 = fmaxf(mt2, fmaxf(sc[na][2], sc[na][3]));
            }
            mt1 = fmaxf(mt1, __shfl_xor_sync(FULL, mt1, 1));
            mt1 = fmaxf(mt1, __shfl_xor_sync(FULL, mt1, 2));
            mt2 = fmaxf(mt2, __shfl_xor_sync(FULL, mt2, 1));
            mt2 = fmaxf(mt2, __shfl_xor_sync(FULL, mt2, 2));

            float mn1 = fmaxf(m1, mt1);
            float mn2 = fmaxf(m2, mt2);
            float c1 = __expf(m1 - mn1);
            float c2 = __expf(m2 - mn2);
            m1 = mn1; m2 = mn2;

            // ---- exp + P conversion (C-frag -> A-frag via quad shuffles) ----
            int basel = lane & ~3;
            int srcA  = basel + (tig >> 1);
            int srcB  = srcA + 2;
            int comp  = tig & 1;
            uint32_t pa[8][4];
            float pt1 = 0.f, pt2 = 0.f;
            #pragma unroll
            for (int na = 0; na < 8; na++) {
                float e0 = __expf(sc[na][0] - mn1);
                float e1 = __expf(sc[na][1] - mn1);
                float e2 = __expf(sc[na][2] - mn2);
                float e3 = __expf(sc[na][3] - mn2);
                pt1 += e0 + e1;
                pt2 += e2 + e3;
                float x0 = __shfl_sync(FULL, e0, srcA);
                float x1 = __shfl_sync(FULL, e1, srcA);
                float y0 = __shfl_sync(FULL, e2, srcA);
                float y1 = __shfl_sync(FULL, e3, srcA);
                float z0 = __shfl_sync(FULL, e0, srcB);
                float z1 = __shfl_sync(FULL, e1, srcB);
                float w0 = __shfl_sync(FULL, e2, srcB);
                float w1 = __shfl_sync(FULL, e3, srcB);
                pa[na][0] = __float_as_uint(comp ? x1 : x0);
                pa[na][1] = __float_as_uint(comp ? y1 : y0);
                pa[na][2] = __float_as_uint(comp ? z1 : z0);
                pa[na][3] = __float_as_uint(comp ? w1 : w0);
            }
            pt1 += __shfl_xor_sync(FULL, pt1, 1);
            pt1 += __shfl_xor_sync(FULL, pt1, 2);
            pt2 += __shfl_xor_sync(FULL, pt2, 1);
            pt2 += __shfl_xor_sync(FULL, pt2, 2);
            l1 = l1 * c1 + pt1;
            l2 = l2 * c2 + pt2;

            #pragma unroll
            for (int na = 0; na < 8; na++) {
                oacc[na][0] *= c1; oacc[na][1] *= c1;
                oacc[na][2] *= c2; oacc[na][3] *= c2;
            }

            // ---- O += P @ V ----
            #pragma unroll
            for (int ka = 0; ka < 8; ka++) {
                #pragma unroll
                for (int na = 0; na < 8; na++) {
                    uint32_t b0 = __float_as_uint(Vs[(ka * 8 + tig) * F_STR + na * 8 + gid]);
                    uint32_t b1 = __float_as_uint(Vs[(ka * 8 + tig + 4) * F_STR + na * 8 + gid]);
                    MMA_TF32(oacc[na], pa[ka], b0, b1);
                }
            }
        }
        __syncthreads();
    }

    float inv1 = 1.0f / l1;
    float inv2 = 1.0f / l2;
    float* o1 = O + ((size_t)b * S + r1) * D + h * HD;
    float* o2 = O + ((size_t)b * S + r2) * D + h * HD;
    #pragma unroll
    for (int na = 0; na < 8; na++) {
        int col = na * 8 + 2 * tig;
        *(float2*)(o1 + col) = make_float2(oacc[na][0] * inv1, oacc[na][1] * inv1);
        *(float2*)(o2 + col) = make_float2(oacc[na][2] * inv2, oacc[na][3] * inv2);
    }
}

// ---------------- launch ----------------------------------------------------
extern "C" void kernel_launch(void* const* d_in, const int* in_sizes, int n_in,
                              void* d_out, int out_size)
{
    const float* x    = (const float*)d_in[0];
    const int*   am   = (const int*)  d_in[1];
    const float* ln1g = (const float*)d_in[2];
    const float* ln1b = (const float*)d_in[3];
    const float* ln2g = (const float*)d_in[4];
    const float* ln2b = (const float*)d_in[5];
    const float* Wq   = (const float*)d_in[6];
    const float* bq   = (const float*)d_in[7];
    const float* Wk   = (const float*)d_in[8];
    const float* bk   = (const float*)d_in[9];
    const float* Wv   = (const float*)d_in[10];
    const float* bv   = (const float*)d_in[11];
    const float* Wo   = (const float*)d_in[12];
    const float* bo   = (const float*)d_in[13];
    const float* W1   = (const float*)d_in[14];
    const float* b1   = (const float*)d_in[15];
    const float* W2   = (const float*)d_in[16];
    const float* b2   = (const float*)d_in[17];
    float* out = (float*)d_out;

    float *h, *qkv, *ctx, *x1, *h2, *ff, *wqkv, *bqkv;
    cudaGetSymbolAddress((void**)&h,    g_h);
    cudaGetSymbolAddress((void**)&qkv,  g_qkv);
    cudaGetSymbolAddress((void**)&ctx,  g_ctx);
    cudaGetSymbolAddress((void**)&x1,   g_x1);
    cudaGetSymbolAddress((void**)&h2,   g_h2);
    cudaGetSymbolAddress((void**)&ff,   g_ff);
    cudaGetSymbolAddress((void**)&wqkv, g_wqkv);
    cudaGetSymbolAddress((void**)&bqkv, g_bqkv);

    cudaFuncSetAttribute(mma_gemm<1>,
        cudaFuncAttributeMaxDynamicSharedMemorySize, GEMM_SMEM);
    cudaFuncSetAttribute(mma_gemm<2>,
        cudaFuncAttributeMaxDynamicSharedMemorySize, GEMM_SMEM);
    cudaFuncSetAttribute(mma_gemm<3>,
        cudaFuncAttributeMaxDynamicSharedMemorySize, GEMM_SMEM);
    cudaFuncSetAttribute(flash_mma,
        cudaFuncAttributeMaxDynamicSharedMemorySize, FLASH_SMEM);

    dim3 blk(256);
    dim3 gQKV(QKVW / 128, NTOK / 128);   // 18 x 64
    dim3 gD(D / 128, NTOK / 128);        // 6 x 64
    dim3 gF(DFF / 128, NTOK / 128);      // 24 x 64

    // pack fused QKV weights/bias
    pack_qkv_w<<<(D * D + 255) / 256, blk>>>(Wq, Wk, Wv, wqkv);
    pack_qkv_b<<<(D + 255) / 256, blk>>>(bq, bk, bv, bqkv);
    // LN1
    ln_kernel<<<NTOK, blk>>>(x, ln1g, ln1b, h);
    // fused QKV projection (tf32-rounded outputs)
    mma_gemm<3><<<gQKV, blk, GEMM_SMEM>>>(NTOK, QKVW, D, h, wqkv, bqkv, nullptr, qkv);
    // attention
    flash_mma<<<dim3(S / 128, H, B), blk, FLASH_SMEM>>>(qkv, am, ctx);
    // O projection + residual(x)
    mma_gemm<2><<<gD, blk, GEMM_SMEM>>>(NTOK, D, D, ctx, Wo, bo, x, x1);
    // LN2
    ln_kernel<<<NTOK, blk>>>(x1, ln2g, ln2b, h2);
    // FFN
    mma_gemm<1><<<gF, blk, GEMM_SMEM>>>(NTOK, DFF, D, h2, W1, b1, nullptr, ff);
    mma_gemm<2><<<gD, blk, GEMM_SMEM>>>(NTOK, D, DFF, ff, W2, b2, x1, out);
}

// round 9
// speedup vs baseline: 1.0538x; 1.0538x over previous
#include <cuda_runtime.h>
#include <math.h>
#include <stdint.h>

// Problem constants
static constexpr int D    = 768;
static constexpr int H    = 12;
static constexpr int HD   = 64;
static constexpr int DFF  = 3072;
static constexpr int B    = 2;
static constexpr int S    = 4096;
static constexpr int NTOK = B * S;   // 8192
static constexpr int QKVW = 3 * D;   // 2304

// ---------------- scratch (static device globals; no allocation) ------------
__device__ float g_h   [NTOK * D];
__device__ float g_qkv [NTOK * QKVW];
__device__ float g_ctx [NTOK * D];
__device__ float g_x1  [NTOK * D];
__device__ float g_h2  [NTOK * D];
__device__ float g_ff  [NTOK * DFF];
__device__ float g_wqkv[D * QKVW];
__device__ float g_bqkv[QKVW];
__device__ float g_wo  [D * D];
__device__ float g_w1  [D * DFF];
__device__ float g_w2  [DFF * D];

// ---------------- cp.async helpers ------------------------------------------
#define CP16(dst_u32, src_ptr)                                                 \
    asm volatile("cp.async.cg.shared.global [%0], [%1], 16;"                   \
                 :: "r"(dst_u32), "l"(src_ptr))
#define CP_COMMIT() asm volatile("cp.async.commit_group;")
#define CP_WAIT(N)  asm volatile("cp.async.wait_group %0;" :: "n"(N))

// ---------------- tf32 helpers ----------------------------------------------
__device__ __forceinline__ uint32_t tf32u(float x) {
    asm("cvt.rna.tf32.f32 %0, %0;" : "+f"(x));
    return __float_as_uint(x);
}
__device__ __forceinline__ float tf32f(float x) {
    asm("cvt.rna.tf32.f32 %0, %0;" : "+f"(x));
    return x;
}

#define MMA_TF32(Cr, Ar, B0, B1)                                               \
    asm volatile(                                                              \
        "mma.sync.aligned.m16n8k8.row.col.f32.tf32.tf32.f32 "                  \
        "{%0,%1,%2,%3}, {%4,%5,%6,%7}, {%8,%9}, {%0,%1,%2,%3};"                \
        : "+f"(Cr[0]), "+f"(Cr[1]), "+f"(Cr[2]), "+f"(Cr[3])                   \
        : "r"(Ar[0]), "r"(Ar[1]), "r"(Ar[2]), "r"(Ar[3]),                      \
          "r"(B0), "r"(B1))

// ---------------- weight prep (pack QKV + round-copy, once per launch) ------
__global__ __launch_bounds__(256) void pack_qkv_w(
    const float* __restrict__ Wq, const float* __restrict__ Wk,
    const float* __restrict__ Wv, float* __restrict__ Wp)
{
    int idx = blockIdx.x * 256 + threadIdx.x;   // over D*D
    if (idx >= D * D) return;
    int row = idx / D, col = idx % D;
    float* o = Wp + (size_t)row * QKVW + col;
    o[0]     = tf32f(Wq[idx]);
    o[D]     = tf32f(Wk[idx]);
    o[2 * D] = tf32f(Wv[idx]);
}
__global__ __launch_bounds__(256) void pack_qkv_b(
    const float* __restrict__ bq, const float* __restrict__ bk,
    const float* __restrict__ bv, float* __restrict__ bp)
{
    int i = blockIdx.x * 256 + threadIdx.x;
    if (i < D) { bp[i] = bq[i]; bp[i + D] = bk[i]; bp[i + 2 * D] = bv[i]; }
}
// vectorized tf32 round-copy (n multiple of 4)
__global__ __launch_bounds__(256) void round_copy(
    const float* __restrict__ src, float* __restrict__ dst, int n4)
{
    int i = blockIdx.x * 256 + threadIdx.x;
    if (i >= n4) return;
    float4 v = ((const float4*)src)[i];
    ((float4*)dst)[i] = make_float4(tf32f(v.x), tf32f(v.y), tf32f(v.z), tf32f(v.w));
}

// ---------------- LayerNorm: one block per row, tf32-rounded output ---------
__global__ __launch_bounds__(256) void ln_kernel(
    const float* __restrict__ x,
    const float* __restrict__ gamma,
    const float* __restrict__ beta,
    float* __restrict__ out)
{
    int row = blockIdx.x;
    int tid = threadIdx.x;
    const float* xr = x + (size_t)row * D;

    float v0 = xr[tid];
    float v1 = xr[tid + 256];
    float v2 = xr[tid + 512];
    float s  = v0 + v1 + v2;
    float ss = v0*v0 + v1*v1 + v2*v2;

    #pragma unroll
    for (int off = 16; off; off >>= 1) {
        s  += __shfl_down_sync(0xffffffffu, s,  off);
        ss += __shfl_down_sync(0xffffffffu, ss, off);
    }

    __shared__ float rs[8], rss[8];
    __shared__ float mu_s, rstd_s;
    if ((tid & 31) == 0) { rs[tid >> 5] = s; rss[tid >> 5] = ss; }
    __syncthreads();
    if (tid == 0) {
        float S_ = 0.f, SS_ = 0.f;
        #pragma unroll
        for (int w = 0; w < 8; w++) { S_ += rs[w]; SS_ += rss[w]; }
        float mu  = S_ * (1.0f / (float)D);
        float var = SS_ * (1.0f / (float)D) - mu * mu;
        mu_s   = mu;
        rstd_s = rsqrtf(var + 1e-5f);
    }
    __syncthreads();
    float mu = mu_s, r = rstd_s;

    float* orow = out + (size_t)row * D;
    orow[tid]       = tf32f((v0 - mu) * r * gamma[tid]       + beta[tid]);
    orow[tid + 256] = tf32f((v1 - mu) * r * gamma[tid + 256] + beta[tid + 256]);
    orow[tid + 512] = tf32f((v2 - mu) * r * gamma[tid + 512] + beta[tid + 512]);
}

// ---------------- tf32 MMA GEMM, cp.async 4-stage, 1 sync/iter --------------
// All inputs pre-rounded to tf32 -> plain loads in the inner loop.
// EPI: 0 = bias, 1 = bias+relu+round, 2 = bias+residual, 3 = bias+round
static constexpr int GA_STR = 20;
static constexpr int GB_STR = 136;
static constexpr int GA_SZ  = 128 * GA_STR;
static constexpr int GB_SZ  = 16 * GB_STR;
static constexpr int G_STG  = GA_SZ + GB_SZ;
static constexpr int G_NSTG = 4;
static constexpr int GEMM_SMEM = G_NSTG * G_STG * 4;   // 75776 bytes

template <int EPI>
__global__ __launch_bounds__(256, 2) void mma_gemm(
    int M, int N, int K,
    const float* __restrict__ A,
    const float* __restrict__ Bw,
    const float* __restrict__ bias,
    const float* __restrict__ res,
    float* __restrict__ C)
{
    extern __shared__ float sm[];

    int tid  = threadIdx.x;
    int lane = tid & 31;
    int warp = tid >> 5;
    int wm   = warp >> 2;
    int wn   = warp & 3;
    int gid  = lane >> 2;
    int tig  = lane & 3;

    int bx = blockIdx.x, by = blockIdx.y;
    const float* Ab = A  + (size_t)(by * 128) * K;
    const float* Bb = Bw + bx * 128;

    int arow = tid >> 2;
    int acol = (tid & 3) * 4;
    int brow = tid >> 4;
    int bcol = (tid & 15) * 4;

    const float* ag0 = Ab + (size_t)arow * K + acol;
    const float* ag1 = Ab + (size_t)(arow + 64) * K + acol;
    const float* bg0 = Bb + (size_t)brow * N + bcol;

    uint32_t smb = (uint32_t)__cvta_generic_to_shared(sm);
    uint32_t aoff0 = (arow * GA_STR + acol) * 4;
    uint32_t aoff1 = ((arow + 64) * GA_STR + acol) * 4;
    uint32_t boff0 = (GA_SZ + brow * GB_STR + bcol) * 4;
    uint32_t boff1 = boff0 + 64 * 4;

    auto issue = [&](int t) {
        uint32_t s = smb + (uint32_t)((t & 3) * G_STG * 4);
        CP16(s + aoff0, ag0 + t * 16);
        CP16(s + aoff1, ag1 + t * 16);
        const float* bp = bg0 + (size_t)t * 16 * N;
        CP16(s + boff0, bp);
        CP16(s + boff1, bp + 64);
        CP_COMMIT();
    };

    float acc[4][4][4];
    #pragma unroll
    for (int i = 0; i < 4; i++)
        #pragma unroll
        for (int j = 0; j < 4; j++)
            #pragma unroll
            for (int r = 0; r < 4; r++) acc[i][j][r] = 0.f;

    int ntiles = K >> 4;
    issue(0);
    issue(1);
    issue(2);

    for (int t = 0; t < ntiles; t++) {
        CP_WAIT(2);
        __syncthreads();
        if (t + 3 < ntiles) issue(t + 3); else CP_COMMIT();

        const float* As = sm + (t & 3) * G_STG;
        const float* Bs = As + GA_SZ;

        #pragma unroll
        for (int ks = 0; ks < 2; ks++) {
            int k0 = ks * 8;
            uint32_t af[4][4];
            uint32_t bf[4][2];
            #pragma unroll
            for (int ma = 0; ma < 4; ma++) {
                int r = wm * 64 + ma * 16 + gid;
                af[ma][0] = __float_as_uint(As[r * GA_STR + k0 + tig]);
                af[ma][1] = __float_as_uint(As[(r + 8) * GA_STR + k0 + tig]);
                af[ma][2] = __float_as_uint(As[r * GA_STR + k0 + tig + 4]);
                af[ma][3] = __float_as_uint(As[(r + 8) * GA_STR + k0 + tig + 4]);
            }
            #pragma unroll
            for (int na = 0; na < 4; na++) {
                int c = wn * 32 + na * 8 + gid;
                bf[na][0] = __float_as_uint(Bs[(k0 + tig) * GB_STR + c]);
                bf[na][1] = __float_as_uint(Bs[(k0 + tig + 4) * GB_STR + c]);
            }
            #pragma unroll
            for (int ma = 0; ma < 4; ma++)
                #pragma unroll
                for (int na = 0; na < 4; na++)
                    MMA_TF32(acc[ma][na], af[ma], bf[na][0], bf[na][1]);
        }
        // no trailing sync: with 4 stages, issue(t+3) at iter t writes buffer
        // (t-1)%4 whose readers all passed the sync at the top of this iter.
    }

    #pragma unroll
    for (int ma = 0; ma < 4; ma++) {
        #pragma unroll
        for (int na = 0; na < 4; na++) {
            int row = by * 128 + wm * 64 + ma * 16 + gid;
            int col = bx * 128 + wn * 32 + na * 8 + 2 * tig;
            float b0v = bias[col], b1v = bias[col + 1];
            float v0 = acc[ma][na][0] + b0v;
            float v1 = acc[ma][na][1] + b1v;
            float v2 = acc[ma][na][2] + b0v;
            float v3 = acc[ma][na][3] + b1v;
            if (EPI == 1) {
                v0 = tf32f(fmaxf(v0, 0.f)); v1 = tf32f(fmaxf(v1, 0.f));
                v2 = tf32f(fmaxf(v2, 0.f)); v3 = tf32f(fmaxf(v3, 0.f));
            }
            if (EPI == 2) {
                const float* r0 = res + (size_t)row * N + col;
                const float* r1 = res + (size_t)(row + 8) * N + col;
                v0 += r0[0]; v1 += r0[1];
                v2 += r1[0]; v3 += r1[1];
            }
            if (EPI == 3) {
                v0 = tf32f(v0); v1 = tf32f(v1);
                v2 = tf32f(v2); v3 = tf32f(v3);
            }
            *(float2*)(C + (size_t)row * N + col)       = make_float2(v0, v1);
            *(float2*)(C + (size_t)(row + 8) * N + col) = make_float2(v2, v3);
        }
    }
}

// ---------------- Flash attention, tf32 MMA + cp.async double buffer --------
// grid = (S/128, H, B), block = 256 (8 warps). qb reversed so the heaviest
// causal blocks launch first (better wave packing of the triangular load).
static constexpr int F_STR  = 68;
static constexpr int F_TSZ  = 64 * F_STR;
static constexpr int F_STG  = 2 * F_TSZ;
static constexpr int FLASH_SMEM = 2 * F_STG * 4;

__global__ __launch_bounds__(256, 1) void flash_mma(
    const float* __restrict__ QKV,
    const int*   __restrict__ am,
    float* __restrict__ O)
{
    extern __shared__ float sm[];
    __shared__ float addm[2][64];

    const unsigned FULL = 0xffffffffu;
    int qb = gridDim.x - 1 - blockIdx.x;   // heavy blocks first
    int h = blockIdx.y, b = blockIdx.z;
    int tid  = threadIdx.x;
    int lane = tid & 31;
    int warp = tid >> 5;
    int gid  = lane >> 2;
    int tig  = lane & 3;

    int row0 = qb * 128 + warp * 16;
    int r1 = row0 + gid;
    int r2 = r1 + 8;
    int wrow_max = row0 + 15;

    const float scale = 0.125f;

    int lr = tid >> 2;
    int lc = (tid & 3) * 16;
    uint32_t smb = (uint32_t)__cvta_generic_to_shared(sm);
    uint32_t koff = (lr * F_STR + lc) * 4;
    uint32_t voff = (F_TSZ + lr * F_STR + lc) * 4;
    const float* kg = QKV + ((size_t)b * S + lr) * QKVW + D     + h * HD + lc;
    const float* vg = QKV + ((size_t)b * S + lr) * QKVW + 2 * D + h * HD + lc;

    auto issueKV = [&](int t) {
        uint32_t s = smb + (uint32_t)((t & 1) * F_STG * 4);
        const float* kp = kg + (size_t)t * 64 * QKVW;
        const float* vp = vg + (size_t)t * 64 * QKVW;
        #pragma unroll
        for (int i = 0; i < 16; i += 4) {
            CP16(s + koff + i * 4, kp + i);
            CP16(s + voff + i * 4, vp + i);
        }
        CP_COMMIT();
    };

    // Q fragments, pre-scaled tf32
    uint32_t qa[8][4];
    {
        const float* q1 = QKV + ((size_t)b * S + r1) * QKVW + h * HD;
        const float* q2 = QKV + ((size_t)b * S + r2) * QKVW + h * HD;
        #pragma unroll
        for (int ka = 0; ka < 8; ka++) {
            qa[ka][0] = tf32u(q1[ka * 8 + tig]     * scale);
            qa[ka][1] = tf32u(q2[ka * 8 + tig]     * scale);
            qa[ka][2] = tf32u(q1[ka * 8 + tig + 4] * scale);
            qa[ka][3] = tf32u(q2[ka * 8 + tig + 4] * scale);
        }
    }

    float m1 = -1e30f, m2 = -1e30f, l1 = 0.f, l2 = 0.f;
    float oacc[8][4];
    #pragma unroll
    for (int i = 0; i < 8; i++)
        #pragma unroll
        for (int j = 0; j < 4; j++) oacc[i][j] = 0.f;

    int ntiles = qb * 2 + 2;
    issueKV(0);
    if (tid < 64)
        addm[0][tid] = (am[(size_t)b * S + tid] != 0) ? 0.f : -1e30f;

    for (int kv = 0; kv < ntiles; kv++) {
        CP_WAIT(0);
        __syncthreads();
        if (kv + 1 < ntiles) {
            issueKV(kv + 1);
            if (tid < 64)
                addm[(kv + 1) & 1][tid] =
                    (am[(size_t)b * S + (kv + 1) * 64 + tid] != 0) ? 0.f : -1e30f;
        }

        if (kv * 64 <= wrow_max) {
            const float* Ks = sm + (kv & 1) * F_STG;
            const float* Vs = Ks + F_TSZ;
            const float* amr = addm[kv & 1];

            // ---- S = Q @ K^T ----
            float sc[8][4];
            #pragma unroll
            for (int na = 0; na < 8; na++)
                #pragma unroll
                for (int j = 0; j < 4; j++) sc[na][j] = 0.f;

            #pragma unroll
            for (int ka = 0; ka < 8; ka++) {
                #pragma unroll
                for (int na = 0; na < 8; na++) {
                    uint32_t b0 = __float_as_uint(Ks[(na * 8 + gid) * F_STR + ka * 8 + tig]);
                    uint32_t b1 = __float_as_uint(Ks[(na * 8 + gid) * F_STR + ka * 8 + tig + 4]);
                    MMA_TF32(sc[na], qa[ka], b0, b1);
                }
            }

            // ---- mask + row max ----
            float mt1 = -1e30f, mt2 = -1e30f;
            #pragma unroll
            for (int na = 0; na < 8; na++) {
                int key0 = kv * 64 + na * 8 + 2 * tig;
                float a0 = amr[na * 8 + 2 * tig];
                float a1 = amr[na * 8 + 2 * tig + 1];
                sc[na][0] = (key0     <= r1) ? sc[na][0] + a0 : -1e30f;
                sc[na][1] = (key0 + 1 <= r1) ? sc[na][1] + a1 : -1e30f;
                sc[na][2] = (key0     <= r2) ? sc[na][2] + a0 : -1e30f;
                sc[na][3] = (key0 + 1 <= r2) ? sc[na][3] + a1 : -1e30f;
                mt1 = fmaxf(mt1, fmaxf(sc[na][0], sc[na][1]));
                mt2 = fmaxf(mt2, fmaxf(sc[na][2], sc[na][3]));
            }
            mt1 = fmaxf(mt1, __shfl_xor_sync(FULL, mt1, 1));
            mt1 = fmaxf(mt1, __shfl_xor_sync(FULL, mt1, 2));
            mt2 = fmaxf(mt2, __shfl_xor_sync(FULL, mt2, 1));
            mt2 = fmaxf(mt2, __shfl_xor_sync(FULL, mt2, 2));

            float mn1 = fmaxf(m1, mt1);
            float mn2 = fmaxf(m2, mt2);
            float c1 = __expf(m1 - mn1);
            float c2 = __expf(m2 - mn2);
            m1 = mn1; m2 = mn2;

            // ---- exp + P conversion (C-frag -> A-frag via quad shuffles) ----
            int basel = lane & ~3;
            int srcA  = basel + (tig >> 1);
            int srcB  = srcA + 2;
            int comp  = tig & 1;
            uint32_t pa[8][4];
            float pt1 = 0.f, pt2 = 0.f;
            #pragma unroll
            for (int na = 0; na < 8; na++) {
                float e0 = __expf(sc[na][0] - mn1);
                float e1 = __expf(sc[na][1] - mn1);
                float e2 = __expf(sc[na][2] - mn2);
                float e3 = __expf(sc[na][3] - mn2);
                pt1 += e0 + e1;
                pt2 += e2 + e3;
                float x0 = __shfl_sync(FULL, e0, srcA);
                float x1 = __shfl_sync(FULL, e1, srcA);
                float y0 = __shfl_sync(FULL, e2, srcA);
                float y1 = __shfl_sync(FULL, e3, srcA);
                float z0 = __shfl_sync(FULL, e0, srcB);
                float z1 = __shfl_sync(FULL, e1, srcB);
                float w0 = __shfl_sync(FULL, e2, srcB);
                float w1 = __shfl_sync(FULL, e3, srcB);
                pa[na][0] = __float_as_uint(comp ? x1 : x0);
                pa[na][1] = __float_as_uint(comp ? y1 : y0);
                pa[na][2] = __float_as_uint(comp ? z1 : z0);
                pa[na][3] = __float_as_uint(comp ? w1 : w0);
            }
            pt1 += __shfl_xor_sync(FULL, pt1, 1);
            pt1 += __shfl_xor_sync(FULL, pt1, 2);
            pt2 += __shfl_xor_sync(FULL, pt2, 1);
            pt2 += __shfl_xor_sync(FULL, pt2, 2);
            l1 = l1 * c1 + pt1;
            l2 = l2 * c2 + pt2;

            #pragma unroll
            for (int na = 0; na < 8; na++) {
                oacc[na][0] *= c1; oacc[na][1] *= c1;
                oacc[na][2] *= c2; oacc[na][3] *= c2;
            }

            // ---- O += P @ V ----
            #pragma unroll
            for (int ka = 0; ka < 8; ka++) {
                #pragma unroll
                for (int na = 0; na < 8; na++) {
                    uint32_t b0 = __float_as_uint(Vs[(ka * 8 + tig) * F_STR + na * 8 + gid]);
                    uint32_t b1 = __float_as_uint(Vs[(ka * 8 + tig + 4) * F_STR + na * 8 + gid]);
                    MMA_TF32(oacc[na], pa[ka], b0, b1);
                }
            }
        }
        __syncthreads();
    }

    float inv1 = 1.0f / l1;
    float inv2 = 1.0f / l2;
    float* o1 = O + ((size_t)b * S + r1) * D + h * HD;
    float* o2 = O + ((size_t)b * S + r2) * D + h * HD;
    #pragma unroll
    for (int na = 0; na < 8; na++) {
        int col = na * 8 + 2 * tig;
        *(float2*)(o1 + col) = make_float2(tf32f(oacc[na][0] * inv1),
                                           tf32f(oacc[na][1] * inv1));
        *(float2*)(o2 + col) = make_float2(tf32f(oacc[na][2] * inv2),
                                           tf32f(oacc[na][3] * inv2));
    }
}

// ---------------- launch ----------------------------------------------------
extern "C" void kernel_launch(void* const* d_in, const int* in_sizes, int n_in,
                              void* d_out, int out_size)
{
    const float* x    = (const float*)d_in[0];
    const int*   am   = (const int*)  d_in[1];
    const float* ln1g = (const float*)d_in[2];
    const float* ln1b = (const float*)d_in[3];
    const float* ln2g = (const float*)d_in[4];
    const float* ln2b = (const float*)d_in[5];
    const float* Wq   = (const float*)d_in[6];
    const float* bq   = (const float*)d_in[7];
    const float* Wk   = (const float*)d_in[8];
    const float* bk   = (const float*)d_in[9];
    const float* Wv   = (const float*)d_in[10];
    const float* bv   = (const float*)d_in[11];
    const float* Wo   = (const float*)d_in[12];
    const float* bo   = (const float*)d_in[13];
    const float* W1   = (const float*)d_in[14];
    const float* b1   = (const float*)d_in[15];
    const float* W2   = (const float*)d_in[16];
    const float* b2   = (const float*)d_in[17];
    float* out = (float*)d_out;

    float *h, *qkv, *ctx, *x1, *h2, *ff, *wqkv, *bqkv, *wo, *w1, *w2;
    cudaGetSymbolAddress((void**)&h,    g_h);
    cudaGetSymbolAddress((void**)&qkv,  g_qkv);
    cudaGetSymbolAddress((void**)&ctx,  g_ctx);
    cudaGetSymbolAddress((void**)&x1,   g_x1);
    cudaGetSymbolAddress((void**)&h2,   g_h2);
    cudaGetSymbolAddress((void**)&ff,   g_ff);
    cudaGetSymbolAddress((void**)&wqkv, g_wqkv);
    cudaGetSymbolAddress((void**)&bqkv, g_bqkv);
    cudaGetSymbolAddress((void**)&wo,   g_wo);
    cudaGetSymbolAddress((void**)&w1,   g_w1);
    cudaGetSymbolAddress((void**)&w2,   g_w2);

    cudaFuncSetAttribute(mma_gemm<1>,
        cudaFuncAttributeMaxDynamicSharedMemorySize, GEMM_SMEM);
    cudaFuncSetAttribute(mma_gemm<2>,
        cudaFuncAttributeMaxDynamicSharedMemorySize, GEMM_SMEM);
    cudaFuncSetAttribute(mma_gemm<3>,
        cudaFuncAttributeMaxDynamicSharedMemorySize, GEMM_SMEM);
    cudaFuncSetAttribute(flash_mma,
        cudaFuncAttributeMaxDynamicSharedMemorySize, FLASH_SMEM);

    dim3 blk(256);
    dim3 gQKV(QKVW / 128, NTOK / 128);   // 18 x 64
    dim3 gD(D / 128, NTOK / 128);        // 6 x 64
    dim3 gF(DFF / 128, NTOK / 128);      // 24 x 64

    // weight prep: pack QKV (rounded) + round-copy Wo/W1/W2
    pack_qkv_w<<<(D * D + 255) / 256, blk>>>(Wq, Wk, Wv, wqkv);
    pack_qkv_b<<<(D + 255) / 256, blk>>>(bq, bk, bv, bqkv);
    round_copy<<<(D * D / 4 + 255) / 256, blk>>>(Wo, wo, D * D / 4);
    round_copy<<<(D * DFF / 4 + 255) / 256, blk>>>(W1, w1, D * DFF / 4);
    round_copy<<<(DFF * D / 4 + 255) / 256, blk>>>(W2, w2, DFF * D / 4);
    // LN1 (rounded output)
    ln_kernel<<<NTOK, blk>>>(x, ln1g, ln1b, h);
    // fused QKV projection (rounded outputs)
    mma_gemm<3><<<gQKV, blk, GEMM_SMEM>>>(NTOK, QKVW, D, h, wqkv, bqkv, nullptr, qkv);
    // attention (rounded ctx output)
    flash_mma<<<dim3(S / 128, H, B), blk, FLASH_SMEM>>>(qkv, am, ctx);
    // O projection + residual(x)
    mma_gemm<2><<<gD, blk, GEMM_SMEM>>>(NTOK, D, D, ctx, wo, bo, x, x1);
    // LN2 (rounded output)
    ln_kernel<<<NTOK, blk>>>(x1, ln2g, ln2b, h2);
    // FFN
    mma_gemm<1><<<gF, blk, GEMM_SMEM>>>(NTOK, DFF, D, h2, w1, b1, nullptr, ff);
    mma_gemm<2><<<gD, blk, GEMM_SMEM>>>(NTOK, D, DFF, ff, w2, b2, x1, out);
}

// round 10
// speedup vs baseline: 1.0718x; 1.0171x over previous
#include <cuda_runtime.h>
#include <math.h>
#include <stdint.h>

// Problem constants
static constexpr int D    = 768;
static constexpr int H    = 12;
static constexpr int HD   = 64;
static constexpr int DFF  = 3072;
static constexpr int B    = 2;
static constexpr int S    = 4096;
static constexpr int NTOK = B * S;   // 8192
static constexpr int QKVW = 3 * D;   // 2304

// ---------------- scratch (static device globals; no allocation) ------------
__device__ float g_h   [NTOK * D];
__device__ float g_qkv [NTOK * QKVW];
__device__ float g_ctx [NTOK * D];
__device__ float g_x1  [NTOK * D];
__device__ float g_h2  [NTOK * D];
__device__ float g_ff  [NTOK * DFF];
__device__ float g_wqkv[D * QKVW];
__device__ float g_bqkv[QKVW];
__device__ float g_wo  [D * D];
__device__ float g_w1  [D * DFF];
__device__ float g_w2  [DFF * D];

// ---------------- cp.async helpers ------------------------------------------
#define CP16(dst_u32, src_ptr)                                                 \
    asm volatile("cp.async.cg.shared.global [%0], [%1], 16;"                   \
                 :: "r"(dst_u32), "l"(src_ptr))
#define CP_COMMIT() asm volatile("cp.async.commit_group;")
#define CP_WAIT(N)  asm volatile("cp.async.wait_group %0;" :: "n"(N))

// ---------------- tf32 / fast-exp helpers ------------------------------------
__device__ __forceinline__ uint32_t tf32u(float x) {
    asm("cvt.rna.tf32.f32 %0, %0;" : "+f"(x));
    return __float_as_uint(x);
}
__device__ __forceinline__ float tf32f(float x) {
    asm("cvt.rna.tf32.f32 %0, %0;" : "+f"(x));
    return x;
}
__device__ __forceinline__ float ex2(float x) {   // 2^x, single MUFU op
    asm("ex2.approx.ftz.f32 %0, %0;" : "+f"(x));
    return x;
}

#define MMA_TF32(Cr, Ar, B0, B1)                                               \
    asm volatile(                                                              \
        "mma.sync.aligned.m16n8k8.row.col.f32.tf32.tf32.f32 "                  \
        "{%0,%1,%2,%3}, {%4,%5,%6,%7}, {%8,%9}, {%0,%1,%2,%3};"                \
        : "+f"(Cr[0]), "+f"(Cr[1]), "+f"(Cr[2]), "+f"(Cr[3])                   \
        : "r"(Ar[0]), "r"(Ar[1]), "r"(Ar[2]), "r"(Ar[3]),                      \
          "r"(B0), "r"(B1))

// ---------------- weight prep (pack QKV + round-copy, once per launch) ------
__global__ __launch_bounds__(256) void pack_qkv_w(
    const float* __restrict__ Wq, const float* __restrict__ Wk,
    const float* __restrict__ Wv, float* __restrict__ Wp)
{
    int idx = blockIdx.x * 256 + threadIdx.x;
    if (idx >= D * D) return;
    int row = idx / D, col = idx % D;
    float* o = Wp + (size_t)row * QKVW + col;
    o[0]     = tf32f(Wq[idx]);
    o[D]     = tf32f(Wk[idx]);
    o[2 * D] = tf32f(Wv[idx]);
}
__global__ __launch_bounds__(256) void pack_qkv_b(
    const float* __restrict__ bq, const float* __restrict__ bk,
    const float* __restrict__ bv, float* __restrict__ bp)
{
    int i = blockIdx.x * 256 + threadIdx.x;
    if (i < D) { bp[i] = bq[i]; bp[i + D] = bk[i]; bp[i + 2 * D] = bv[i]; }
}
__global__ __launch_bounds__(256) void round_copy(
    const float* __restrict__ src, float* __restrict__ dst, int n4)
{
    int i = blockIdx.x * 256 + threadIdx.x;
    if (i >= n4) return;
    float4 v = ((const float4*)src)[i];
    ((float4*)dst)[i] = make_float4(tf32f(v.x), tf32f(v.y), tf32f(v.z), tf32f(v.w));
}

// ---------------- LayerNorm: one block per row, tf32-rounded output ---------
__global__ __launch_bounds__(256) void ln_kernel(
    const float* __restrict__ x,
    const float* __restrict__ gamma,
    const float* __restrict__ beta,
    float* __restrict__ out)
{
    int row = blockIdx.x;
    int tid = threadIdx.x;
    const float* xr = x + (size_t)row * D;

    float v0 = xr[tid];
    float v1 = xr[tid + 256];
    float v2 = xr[tid + 512];
    float s  = v0 + v1 + v2;
    float ss = v0*v0 + v1*v1 + v2*v2;

    #pragma unroll
    for (int off = 16; off; off >>= 1) {
        s  += __shfl_down_sync(0xffffffffu, s,  off);
        ss += __shfl_down_sync(0xffffffffu, ss, off);
    }

    __shared__ float rs[8], rss[8];
    __shared__ float mu_s, rstd_s;
    if ((tid & 31) == 0) { rs[tid >> 5] = s; rss[tid >> 5] = ss; }
    __syncthreads();
    if (tid == 0) {
        float S_ = 0.f, SS_ = 0.f;
        #pragma unroll
        for (int w = 0; w < 8; w++) { S_ += rs[w]; SS_ += rss[w]; }
        float mu  = S_ * (1.0f / (float)D);
        float var = SS_ * (1.0f / (float)D) - mu * mu;
        mu_s   = mu;
        rstd_s = rsqrtf(var + 1e-5f);
    }
    __syncthreads();
    float mu = mu_s, r = rstd_s;

    float* orow = out + (size_t)row * D;
    orow[tid]       = tf32f((v0 - mu) * r * gamma[tid]       + beta[tid]);
    orow[tid + 256] = tf32f((v1 - mu) * r * gamma[tid + 256] + beta[tid + 256]);
    orow[tid + 512] = tf32f((v2 - mu) * r * gamma[tid + 512] + beta[tid + 512]);
}

// ---------------- tf32 MMA GEMM, 128 threads, 64x64 warp tiles --------------
// 128x128 CTA tile, BK=16, 4 warps (2x2), warp tile 64x64 (4x8 m16n8k8).
// Per k8-step: 32 MMA vs 32 LDS (was 16 vs 24) -> tensor-pipe friendly.
// EPI: 0 = bias, 1 = bias+relu+round, 2 = bias+residual, 3 = bias+round
static constexpr int GA_STR = 20;
static constexpr int GB_STR = 136;
static constexpr int GA_SZ  = 128 * GA_STR;
static constexpr int GB_SZ  = 16 * GB_STR;
static constexpr int G_STG  = GA_SZ + GB_SZ;
static constexpr int G_NSTG = 4;
static constexpr int GEMM_SMEM = G_NSTG * G_STG * 4;   // 75776 bytes

template <int EPI>
__global__ __launch_bounds__(128, 2) void mma_gemm(
    int M, int N, int K,
    const float* __restrict__ A,
    const float* __restrict__ Bw,
    const float* __restrict__ bias,
    const float* __restrict__ res,
    float* __restrict__ C)
{
    extern __shared__ float sm[];

    int tid  = threadIdx.x;
    int lane = tid & 31;
    int warp = tid >> 5;       // 0..3
    int wm   = warp >> 1;      // 0..1
    int wn   = warp & 1;       // 0..1
    int gid  = lane >> 2;      // 0..7
    int tig  = lane & 3;       // 0..3

    int bx = blockIdx.x, by = blockIdx.y;
    const float* Ab = A  + (size_t)(by * 128) * K;
    const float* Bb = Bw + bx * 128;

    int arow = tid >> 2;            // 0..31 (+32,+64,+96)
    int acol = (tid & 3) * 4;
    int brow = tid >> 4;            // 0..7 (+8)
    int bcol = (tid & 15) * 4;      // 0..60 (+64)

    const float* ag0 = Ab + (size_t)arow * K + acol;
    const float* bg0 = Bb + (size_t)brow * N + bcol;

    uint32_t smb = (uint32_t)__cvta_generic_to_shared(sm);
    uint32_t aoff0 = (arow * GA_STR + acol) * 4;
    uint32_t boff0 = (GA_SZ + brow * GB_STR + bcol) * 4;

    auto issue = [&](int t) {
        uint32_t s = smb + (uint32_t)((t & 3) * G_STG * 4);
        const float* ap = ag0 + t * 16;
        #pragma unroll
        for (int rr = 0; rr < 4; rr++)
            CP16(s + aoff0 + rr * 32 * GA_STR * 4, ap + (size_t)rr * 32 * K);
        const float* bp = bg0 + (size_t)t * 16 * N;
        CP16(s + boff0,                     bp);
        CP16(s + boff0 + 8 * GB_STR * 4,    bp + (size_t)8 * N);
        CP16(s + boff0 + 64 * 4,            bp + 64);
        CP16(s + boff0 + 8 * GB_STR * 4 + 64 * 4, bp + (size_t)8 * N + 64);
        CP_COMMIT();
    };

    float acc[4][8][4];
    #pragma unroll
    for (int i = 0; i < 4; i++)
        #pragma unroll
        for (int j = 0; j < 8; j++)
            #pragma unroll
            for (int r = 0; r < 4; r++) acc[i][j][r] = 0.f;

    int ntiles = K >> 4;
    issue(0);
    issue(1);
    issue(2);

    for (int t = 0; t < ntiles; t++) {
        CP_WAIT(2);
        __syncthreads();
        if (t + 3 < ntiles) issue(t + 3); else CP_COMMIT();

        const float* As = sm + (t & 3) * G_STG;
        const float* Bs = As + GA_SZ;

        #pragma unroll
        for (int ks = 0; ks < 2; ks++) {
            int k0 = ks * 8;
            uint32_t af[4][4];
            uint32_t bf[8][2];
            #pragma unroll
            for (int ma = 0; ma < 4; ma++) {
                int r = wm * 64 + ma * 16 + gid;
                af[ma][0] = __float_as_uint(As[r * GA_STR + k0 + tig]);
                af[ma][1] = __float_as_uint(As[(r + 8) * GA_STR + k0 + tig]);
                af[ma][2] = __float_as_uint(As[r * GA_STR + k0 + tig + 4]);
                af[ma][3] = __float_as_uint(As[(r + 8) * GA_STR + k0 + tig + 4]);
            }
            #pragma unroll
            for (int na = 0; na < 8; na++) {
                int c = wn * 64 + na * 8 + gid;
                bf[na][0] = __float_as_uint(Bs[(k0 + tig) * GB_STR + c]);
                bf[na][1] = __float_as_uint(Bs[(k0 + tig + 4) * GB_STR + c]);
            }
            #pragma unroll
            for (int ma = 0; ma < 4; ma++)
                #pragma unroll
                for (int na = 0; na < 8; na++)
                    MMA_TF32(acc[ma][na], af[ma], bf[na][0], bf[na][1]);
        }
        // no trailing sync: with 4 stages, issue(t+3) at iter t writes buffer
        // (t-1)%4 whose readers all passed the sync at the top of this iter.
    }

    #pragma unroll
    for (int ma = 0; ma < 4; ma++) {
        #pragma unroll
        for (int na = 0; na < 8; na++) {
            int row = by * 128 + wm * 64 + ma * 16 + gid;
            int col = bx * 128 + wn * 64 + na * 8 + 2 * tig;
            float b0v = bias[col], b1v = bias[col + 1];
            float v0 = acc[ma][na][0] + b0v;
            float v1 = acc[ma][na][1] + b1v;
            float v2 = acc[ma][na][2] + b0v;
            float v3 = acc[ma][na][3] + b1v;
            if (EPI == 1) {
                v0 = tf32f(fmaxf(v0, 0.f)); v1 = tf32f(fmaxf(v1, 0.f));
                v2 = tf32f(fmaxf(v2, 0.f)); v3 = tf32f(fmaxf(v3, 0.f));
            }
            if (EPI == 2) {
                const float* r0 = res + (size_t)row * N + col;
                const float* r1 = res + (size_t)(row + 8) * N + col;
                v0 += r0[0]; v1 += r0[1];
                v2 += r1[0]; v3 += r1[1];
            }
            if (EPI == 3) {
                v0 = tf32f(v0); v1 = tf32f(v1);
                v2 = tf32f(v2); v3 = tf32f(v3);
            }
            *(float2*)(C + (size_t)row * N + col)       = make_float2(v0, v1);
            *(float2*)(C + (size_t)(row + 8) * N + col) = make_float2(v2, v3);
        }
    }
}

// ---------------- Flash attention, tf32 MMA, log2-domain softmax ------------
// grid = (S/128, H, B), block = 256 (8 warps). qb reversed (heavy first).
static constexpr int F_STR  = 68;
static constexpr int F_TSZ  = 64 * F_STR;
static constexpr int F_STG  = 2 * F_TSZ;
static constexpr int FLASH_SMEM = 2 * F_STG * 4;

__global__ __launch_bounds__(256, 1) void flash_mma(
    const float* __restrict__ QKV,
    const int*   __restrict__ am,
    float* __restrict__ O)
{
    extern __shared__ float sm[];
    __shared__ float addm[2][64];

    const unsigned FULL = 0xffffffffu;
    int qb = gridDim.x - 1 - blockIdx.x;
    int h = blockIdx.y, b = blockIdx.z;
    int tid  = threadIdx.x;
    int lane = tid & 31;
    int warp = tid >> 5;
    int gid  = lane >> 2;
    int tig  = lane & 3;

    int row0 = qb * 128 + warp * 16;
    int r1 = row0 + gid;
    int r2 = r1 + 8;
    int wrow_max = row0 + 15;

    // scale folded with log2(e): scores live in log2 domain, exp == ex2
    const float scale = 0.125f * 1.44269504088896340736f;

    int lr = tid >> 2;
    int lc = (tid & 3) * 16;
    uint32_t smb = (uint32_t)__cvta_generic_to_shared(sm);
    uint32_t koff = (lr * F_STR + lc) * 4;
    uint32_t voff = (F_TSZ + lr * F_STR + lc) * 4;
    const float* kg = QKV + ((size_t)b * S + lr) * QKVW + D     + h * HD + lc;
    const float* vg = QKV + ((size_t)b * S + lr) * QKVW + 2 * D + h * HD + lc;

    auto issueKV = [&](int t) {
        uint32_t s = smb + (uint32_t)((t & 1) * F_STG * 4);
        const float* kp = kg + (size_t)t * 64 * QKVW;
        const float* vp = vg + (size_t)t * 64 * QKVW;
        #pragma unroll
        for (int i = 0; i < 16; i += 4) {
            CP16(s + koff + i * 4, kp + i);
            CP16(s + voff + i * 4, vp + i);
        }
        CP_COMMIT();
    };

    // Q fragments, pre-scaled (tf32-rounded values * scale, rounded to tf32)
    uint32_t qa[8][4];
    {
        const float* q1 = QKV + ((size_t)b * S + r1) * QKVW + h * HD;
        const float* q2 = QKV + ((size_t)b * S + r2) * QKVW + h * HD;
        #pragma unroll
        for (int ka = 0; ka < 8; ka++) {
            qa[ka][0] = tf32u(q1[ka * 8 + tig]     * scale);
            qa[ka][1] = tf32u(q2[ka * 8 + tig]     * scale);
            qa[ka][2] = tf32u(q1[ka * 8 + tig + 4] * scale);
            qa[ka][3] = tf32u(q2[ka * 8 + tig + 4] * scale);
        }
    }

    float m1 = -1e30f, m2 = -1e30f, l1 = 0.f, l2 = 0.f;
    float oacc[8][4];
    #pragma unroll
    for (int i = 0; i < 8; i++)
        #pragma unroll
        for (int j = 0; j < 4; j++) oacc[i][j] = 0.f;

    int ntiles = qb * 2 + 2;
    issueKV(0);
    if (tid < 64)
        addm[0][tid] = (am[(size_t)b * S + tid] != 0) ? 0.f : -1e30f;

    for (int kv = 0; kv < ntiles; kv++) {
        CP_WAIT(0);
        __syncthreads();
        if (kv + 1 < ntiles) {
            issueKV(kv + 1);
            if (tid < 64)
                addm[(kv + 1) & 1][tid] =
                    (am[(size_t)b * S + (kv + 1) * 64 + tid] != 0) ? 0.f : -1e30f;
        }

        if (kv * 64 <= wrow_max) {
            const float* Ks = sm + (kv & 1) * F_STG;
            const float* Vs = Ks + F_TSZ;
            const float* amr = addm[kv & 1];

            // ---- S = Q @ K^T (log2 domain) ----
            float sc[8][4];
            #pragma unroll
            for (int na = 0; na < 8; na++)
                #pragma unroll
                for (int j = 0; j < 4; j++) sc[na][j] = 0.f;

            #pragma unroll
            for (int ka = 0; ka < 8; ka++) {
                #pragma unroll
                for (int na = 0; na < 8; na++) {
                    uint32_t b0 = __float_as_uint(Ks[(na * 8 + gid) * F_STR + ka * 8 + tig]);
                    uint32_t b1 = __float_as_uint(Ks[(na * 8 + gid) * F_STR + ka * 8 + tig + 4]);
                    MMA_TF32(sc[na], qa[ka], b0, b1);
                }
            }

            // ---- mask + row max ----
            float mt1 = -1e30f, mt2 = -1e30f;
            #pragma unroll
            for (int na = 0; na < 8; na++) {
                int key0 = kv * 64 + na * 8 + 2 * tig;
                float a0 = amr[na * 8 + 2 * tig];
                float a1 = amr[na * 8 + 2 * tig + 1];
                sc[na][0] = (key0     <= r1) ? sc[na][0] + a0 : -1e30f;
                sc[na][1] = (key0 + 1 <= r1) ? sc[na][1] + a1 : -1e30f;
                sc[na][2] = (key0     <= r2) ? sc[na][2] + a0 : -1e30f;
                sc[na][3] = (key0 + 1 <= r2) ? sc[na][3] + a1 : -1e30f;
                mt1 = fmaxf(mt1, fmaxf(sc[na][0], sc[na][1]));
                mt2 = fmaxf(mt2, fmaxf(sc[na][2], sc[na][3]));
            }
            mt1 = fmaxf(mt1, __shfl_xor_sync(FULL, mt1, 1));
            mt1 = fmaxf(mt1, __shfl_xor_sync(FULL, mt1, 2));
            mt2 = fmaxf(mt2, __shfl_xor_sync(FULL, mt2, 1));
            mt2 = fmaxf(mt2, __shfl_xor_sync(FULL, mt2, 2));

            float mn1 = fmaxf(m1, mt1);
            float mn2 = fmaxf(m2, mt2);
            float c1 = ex2(m1 - mn1);
            float c2 = ex2(m2 - mn2);
            m1 = mn1; m2 = mn2;

            // ---- exp2 + P conversion (C-frag -> A-frag via quad shuffles) ----
            int basel = lane & ~3;
            int srcA  = basel + (tig >> 1);
            int srcB  = srcA + 2;
            int comp  = tig & 1;
            uint32_t pa[8][4];
            float pt1 = 0.f, pt2 = 0.f;
            #pragma unroll
            for (int na = 0; na < 8; na++) {
                float e0 = ex2(sc[na][0] - mn1);
                float e1 = ex2(sc[na][1] - mn1);
                float e2 = ex2(sc[na][2] - mn2);
                float e3 = ex2(sc[na][3] - mn2);
                pt1 += e0 + e1;
                pt2 += e2 + e3;
                float x0 = __shfl_sync(FULL, e0, srcA);
                float x1 = __shfl_sync(FULL, e1, srcA);
                float y0 = __shfl_sync(FULL, e2, srcA);
                float y1 = __shfl_sync(FULL, e3, srcA);
                float z0 = __shfl_sync(FULL, e0, srcB);
                float z1 = __shfl_sync(FULL, e1, srcB);
                float w0 = __shfl_sync(FULL, e2, srcB);
                float w1 = __shfl_sync(FULL, e3, srcB);
                pa[na][0] = __float_as_uint(comp ? x1 : x0);
                pa[na][1] = __float_as_uint(comp ? y1 : y0);
                pa[na][2] = __float_as_uint(comp ? z1 : z0);
                pa[na][3] = __float_as_uint(comp ? w1 : w0);
            }
            pt1 += __shfl_xor_sync(FULL, pt1, 1);
            pt1 += __shfl_xor_sync(FULL, pt1, 2);
            pt2 += __shfl_xor_sync(FULL, pt2, 1);
            pt2 += __shfl_xor_sync(FULL, pt2, 2);
            l1 = l1 * c1 + pt1;
            l2 = l2 * c2 + pt2;

            #pragma unroll
            for (int na = 0; na < 8; na++) {
                oacc[na][0] *= c1; oacc[na][1] *= c1;
                oacc[na][2] *= c2; oacc[na][3] *= c2;
            }

            // ---- O += P @ V ----
            #pragma unroll
            for (int ka = 0; ka < 8; ka++) {
                #pragma unroll
                for (int na = 0; na < 8; na++) {
                    uint32_t b0 = __float_as_uint(Vs[(ka * 8 + tig) * F_STR + na * 8 + gid]);
                    uint32_t b1 = __float_as_uint(Vs[(ka * 8 + tig + 4) * F_STR + na * 8 + gid]);
                    MMA_TF32(oacc[na], pa[ka], b0, b1);
                }
            }
        }
        __syncthreads();
    }

    float inv1 = 1.0f / l1;
    float inv2 = 1.0f / l2;
    float* o1 = O + ((size_t)b * S + r1) * D + h * HD;
    float* o2 = O + ((size_t)b * S + r2) * D + h * HD;
    #pragma unroll
    for (int na = 0; na < 8; na++) {
        int col = na * 8 + 2 * tig;
        *(float2*)(o1 + col) = make_float2(tf32f(oacc[na][0] * inv1),
                                           tf32f(oacc[na][1] * inv1));
        *(float2*)(o2 + col) = make_float2(tf32f(oacc[na][2] * inv2),
                                           tf32f(oacc[na][3] * inv2));
    }
}

// ---------------- launch ----------------------------------------------------
extern "C" void kernel_launch(void* const* d_in, const int* in_sizes, int n_in,
                              void* d_out, int out_size)
{
    const float* x    = (const float*)d_in[0];
    const int*   am   = (const int*)  d_in[1];
    const float* ln1g = (const float*)d_in[2];
    const float* ln1b = (const float*)d_in[3];
    const float* ln2g = (const float*)d_in[4];
    const float* ln2b = (const float*)d_in[5];
    const float* Wq   = (const float*)d_in[6];
    const float* bq   = (const float*)d_in[7];
    const float* Wk   = (const float*)d_in[8];
    const float* bk   = (const float*)d_in[9];
    const float* Wv   = (const float*)d_in[10];
    const float* bv   = (const float*)d_in[11];
    const float* Wo   = (const float*)d_in[12];
    const float* bo   = (const float*)d_in[13];
    const float* W1   = (const float*)d_in[14];
    const float* b1   = (const float*)d_in[15];
    const float* W2   = (const float*)d_in[16];
    const float* b2   = (const float*)d_in[17];
    float* out = (float*)d_out;

    float *h, *qkv, *ctx, *x1, *h2, *ff, *wqkv, *bqkv, *wo, *w1, *w2;
    cudaGetSymbolAddress((void**)&h,    g_h);
    cudaGetSymbolAddress((void**)&qkv,  g_qkv);
    cudaGetSymbolAddress((void**)&ctx,  g_ctx);
    cudaGetSymbolAddress((void**)&x1,   g_x1);
    cudaGetSymbolAddress((void**)&h2,   g_h2);
    cudaGetSymbolAddress((void**)&ff,   g_ff);
    cudaGetSymbolAddress((void**)&wqkv, g_wqkv);
    cudaGetSymbolAddress((void**)&bqkv, g_bqkv);
    cudaGetSymbolAddress((void**)&wo,   g_wo);
    cudaGetSymbolAddress((void**)&w1,   g_w1);
    cudaGetSymbolAddress((void**)&w2,   g_w2);

    cudaFuncSetAttribute(mma_gemm<1>,
        cudaFuncAttributeMaxDynamicSharedMemorySize, GEMM_SMEM);
    cudaFuncSetAttribute(mma_gemm<2>,
        cudaFuncAttributeMaxDynamicSharedMemorySize, GEMM_SMEM);
    cudaFuncSetAttribute(mma_gemm<3>,
        cudaFuncAttributeMaxDynamicSharedMemorySize, GEMM_SMEM);
    cudaFuncSetAttribute(flash_mma,
        cudaFuncAttributeMaxDynamicSharedMemorySize, FLASH_SMEM);

    dim3 blkG(128);                      // GEMM: 4 warps / CTA
    dim3 blk(256);
    dim3 gQKV(QKVW / 128, NTOK / 128);   // 18 x 64
    dim3 gD(D / 128, NTOK / 128);        // 6 x 64
    dim3 gF(DFF / 128, NTOK / 128);      // 24 x 64

    // weight prep
    pack_qkv_w<<<(D * D + 255) / 256, blk>>>(Wq, Wk, Wv, wqkv);
    pack_qkv_b<<<(D + 255) / 256, blk>>>(bq, bk, bv, bqkv);
    round_copy<<<(D * D / 4 + 255) / 256, blk>>>(Wo, wo, D * D / 4);
    round_copy<<<(D * DFF / 4 + 255) / 256, blk>>>(W1, w1, D * DFF / 4);
    round_copy<<<(DFF * D / 4 + 255) / 256, blk>>>(W2, w2, DFF * D / 4);
    // LN1
    ln_kernel<<<NTOK, blk>>>(x, ln1g, ln1b, h);
    // fused QKV projection (rounded outputs)
    mma_gemm<3><<<gQKV, blkG, GEMM_SMEM>>>(NTOK, QKVW, D, h, wqkv, bqkv, nullptr, qkv);
    // attention
    flash_mma<<<dim3(S / 128, H, B), blk, FLASH_SMEM>>>(qkv, am, ctx);
    // O projection + residual(x)
    mma_gemm<2><<<gD, blkG, GEMM_SMEM>>>(NTOK, D, D, ctx, wo, bo, x, x1);
    // LN2
    ln_kernel<<<NTOK, blk>>>(x1, ln2g, ln2b, h2);
    // FFN
    mma_gemm<1><<<gF, blkG, GEMM_SMEM>>>(NTOK, DFF, D, h2, w1, b1, nullptr, ff);
    mma_gemm<2><<<gD, blkG, GEMM_SMEM>>>(NTOK, D, DFF, ff, w2, b2, x1, out);
}